// round 15
// baseline (speedup 1.0000x reference)
#include <cuda_runtime.h>
#include <cuda_fp16.h>
#include <cstdint>
#include <cstddef>

// ---------------- problem constants ----------------
#define N_TOK  8192
#define D_INF  4096
#define D_OUTF 4096

// GEMM tiling (known-best): CTA 128x128, warp 32x64 (4x2), BK=64, 3 stages, 2 CTA/SM
#define MT   128
#define NT   128
#define BK   64
#define M_TILES 64      // 8192/128
#define N_TILES 32      // 4096/128
#define KTOT    65      // 64 main K-chunks + 1 LoRA chunk
#define NSTAGE  3

#define A_TILE_ELEMS (MT*BK)        // 8192 halves (16 KB)
#define B_TILE_ELEMS (NT*BK)        // 8192 halves (16 KB)
#define A_TILE_BYTES (A_TILE_ELEMS*2)
#define B_TILE_BYTES (B_TILE_ELEMS*2)
#define STAGE_BYTES  (A_TILE_BYTES + B_TILE_BYTES)       // 32768
#define SMEM_TOTAL   (1024 + 1024 + NSTAGE*STAGE_BYTES)  // 100352 -> 2 CTAs/SM

#define KSPLIT 8

// ---------------- scratch (device globals; no cudaMalloc allowed) ----------------
__device__ __align__(1024) __half gA[(size_t)M_TILES*KTOT*A_TILE_ELEMS];  // x (fp16)
__device__ __align__(1024) __half gB[(size_t)N_TILES*KTOT*B_TILE_ELEMS];  // W (fp16)
__device__ __align__(1024) float g_part[(size_t)KSPLIT*N_TOK*32];         // lora partials

// ---------------- PTX helpers (sm_100 baseline only) ----------------
__device__ __forceinline__ uint32_t smem_u32(const void* p){
    uint32_t a;
    asm("{ .reg .u64 t; cvta.to.shared.u64 t, %1; cvt.u32.u64 %0, t; }" : "=r"(a) : "l"(p));
    return a;
}
__device__ __forceinline__ uint32_t swz128(uint32_t b){ return b ^ ((b >> 3) & 0x70); }

#define MBARRIER_INIT(addr, cnt) \
    asm volatile("mbarrier.init.shared.b64 [%0], %1;" :: "r"(addr), "r"(cnt) : "memory")
#define MBARRIER_EXPECT_TX(addr, bytes) \
    asm volatile("mbarrier.arrive.expect_tx.shared.b64 _, [%0], %1;" :: "r"(addr), "r"(bytes) : "memory")
#define MBARRIER_ARRIVE(addr) \
    asm volatile("mbarrier.arrive.shared.b64 _, [%0];" :: "r"(addr) : "memory")
#define MBARRIER_WAIT_PARITY(addr, par) do {                                     \
    uint32_t _m = (addr); uint32_t _p = (par); uint32_t _d;                      \
    asm volatile("{\n\t.reg .pred p;\n\t"                                        \
        "mbarrier.try_wait.parity.acquire.cta.shared::cta.b64 p, [%1], %2;\n\t"  \
        "selp.b32 %0, 1, 0, p;\n\t}" : "=r"(_d) : "r"(_m), "r"(_p) : "memory");  \
    if (!_d) {                                                                   \
        asm volatile("{\n\t.reg .pred P1;\n\t"                                   \
        "W_%=:\n\t"                                                              \
        "mbarrier.try_wait.parity.acquire.cta.shared::cta.b64 P1, [%0], %1, 0x989680;\n\t" \
        "@P1 bra.uni D_%=;\n\t"                                                  \
        "bra.uni W_%=;\n\t"                                                      \
        "D_%=:\n\t}" :: "r"(_m), "r"(_p) : "memory");                            \
    }                                                                            \
} while (0)

__device__ __forceinline__ void bulk_g2s(uint32_t dst, const void* src, uint32_t bytes, uint32_t mbar){
    asm volatile("cp.async.bulk.shared::cta.global.mbarrier::complete_tx::bytes [%0], [%1], %2, [%3];"
        :: "r"(dst), "l"(src), "r"(bytes), "r"(mbar) : "memory");
}

#define LDSM_X4(r0, r1, r2, r3, addr) \
    asm volatile("ldmatrix.sync.aligned.m8n8.x4.shared.b16 {%0,%1,%2,%3}, [%4];" \
        : "=r"(r0), "=r"(r1), "=r"(r2), "=r"(r3) : "r"(addr))

#define MMA16816(d, a, b) \
    asm volatile("mma.sync.aligned.m16n8k16.row.col.f32.f16.f16.f32 " \
        "{%0,%1,%2,%3}, {%4,%5,%6,%7}, {%8,%9}, {%0,%1,%2,%3};" \
        : "+f"((d)[0]), "+f"((d)[1]), "+f"((d)[2]), "+f"((d)[3]) \
        : "r"((a)[0]), "r"((a)[1]), "r"((a)[2]), "r"((a)[3]), "r"((b)[0]), "r"((b)[1]))

__device__ __forceinline__ uint32_t pack2h(float a, float b){
    __half2 h = __floats2half2_rn(a, b);
    return *reinterpret_cast<uint32_t*>(&h);
}

// ---------------- fused prep: lora split-K partials | x conv | W conv | LoRA-B chunk ----------------
#define LBLK 1024       // 128 token-groups x 8 k-splits
#define XBLK 16384      // (8192*4096/8)/256
#define WBLK 8192       // (4096*4096/8)/256
#define PBLK 1024       // (32*8192)/256

// padded row stride (floats) for float4-aligned smem rows: 36 floats = 144 B (16B-aligned)
#define LSTR 36

__global__ void __launch_bounds__(256) fused_prep_kernel(const float* __restrict__ x,
                                                         const float* __restrict__ W,
                                                         const float* __restrict__ qb,
                                                         const float* __restrict__ sf,
                                                         const float* __restrict__ qa){
    int bid = blockIdx.x, tid = threadIdx.x;
    if (bid < LBLK){
        // ---- LoRA split-K partial: 64 tokens x 512-k slice -> g_part[p][n][j] ----
        // float4-vectorized LDS: per 4-k step, 9 LDS.128 for 32 FMA (vs 36 scalar LDS).
        __shared__ float sqa[32 * LSTR];
        __shared__ float sx[64 * LSTR];
        int n0 = (bid >> 3) * 64;
        int p  = bid & 7;
        int kbase = p * (D_INF / KSPLIT);           // 512-wide slice
        int r   = tid >> 2;            // token row 0..63
        int e   = tid & 3;             // expert
        int jq  = e * 8;
        float acc[8] = {0,0,0,0,0,0,0,0};
        for (int k0 = kbase; k0 < kbase + D_INF / KSPLIT; k0 += 32){
            // fill smem as float4s (each 32-float row = 8 float4, rows 16B-aligned via LSTR)
            {
                int i = tid;                         // 256 float4 = whole sqa tile
                int row = i >> 3, c4 = i & 7;
                *reinterpret_cast<float4*>(&sqa[row * LSTR + c4 * 4]) =
                    *reinterpret_cast<const float4*>(&qa[(size_t)row * D_INF + k0 + c4 * 4]);
            }
            #pragma unroll
            for (int v = 0; v < 2; v++){
                int i = v * 256 + tid;               // 512 float4 = whole sx tile
                int row = i >> 3, c4 = i & 7;
                *reinterpret_cast<float4*>(&sx[row * LSTR + c4 * 4]) =
                    *reinterpret_cast<const float4*>(&x[(size_t)(n0 + row) * D_INF + k0 + c4 * 4]);
            }
            __syncthreads();
            #pragma unroll
            for (int kk4 = 0; kk4 < 8; kk4++){
                float4 xv = *reinterpret_cast<const float4*>(&sx[r * LSTR + kk4 * 4]);
                #pragma unroll
                for (int q = 0; q < 8; q++){
                    float4 qv = *reinterpret_cast<const float4*>(&sqa[(jq + q) * LSTR + kk4 * 4]);
                    // keep EXACT same k-order accumulation as the scalar version
                    acc[q] = fmaf(xv.x, qv.x, acc[q]);
                    acc[q] = fmaf(xv.y, qv.y, acc[q]);
                    acc[q] = fmaf(xv.z, qv.z, acc[q]);
                    acc[q] = fmaf(xv.w, qv.w, acc[q]);
                }
            }
            __syncthreads();
        }
        int n = n0 + r;
        float4* dst = reinterpret_cast<float4*>(g_part + ((size_t)p * N_TOK + n) * 32 + jq);
        dst[0] = make_float4(acc[0], acc[1], acc[2], acc[3]);
        dst[1] = make_float4(acc[4], acc[5], acc[6], acc[7]);
    } else if (bid < LBLK + XBLK){
        size_t t = (size_t)(bid - LBLK) * 256 + tid;
        size_t base = t * 8;                              // k%8==0
        int n = (int)(base >> 12), k = (int)(base & 4095);
        float4 v0 = *reinterpret_cast<const float4*>(x + base);
        float4 v1 = *reinterpret_cast<const float4*>(x + base + 4);
        uint4 h;
        h.x = pack2h(v0.x, v0.y); h.y = pack2h(v0.z, v0.w);
        h.z = pack2h(v1.x, v1.y); h.w = pack2h(v1.z, v1.w);
        int mt = n >> 7, r = n & 127, kc = k >> 6, c = k & 63;
        size_t tile = (size_t)mt * KTOT + kc;
        uint32_t off = swz128((uint32_t)(r * 128 + c * 2));   // 16B-aligned -> stays aligned
        *reinterpret_cast<uint4*>(reinterpret_cast<char*>(&gA[tile * A_TILE_ELEMS]) + off) = h;
    } else if (bid < LBLK + XBLK + WBLK){
        size_t t = (size_t)(bid - LBLK - XBLK) * 256 + tid;
        size_t base = t * 8;
        int o = (int)(base >> 12), k = (int)(base & 4095);
        float4 v0 = *reinterpret_cast<const float4*>(W + base);
        float4 v1 = *reinterpret_cast<const float4*>(W + base + 4);
        uint4 h;
        h.x = pack2h(v0.x, v0.y); h.y = pack2h(v0.z, v0.w);
        h.z = pack2h(v1.x, v1.y); h.w = pack2h(v1.z, v1.w);
        int nt = o >> 7, r = o & 127, kc = k >> 6, c = k & 63;
        size_t tile = (size_t)nt * KTOT + kc;
        uint32_t off = swz128((uint32_t)(r * 128 + c * 2));
        *reinterpret_cast<uint4*>(reinterpret_cast<char*>(&gB[tile * B_TILE_ELEMS]) + off) = h;
    } else {
        int idx = (bid - LBLK - XBLK - WBLK) * 256 + tid; // < 32*8192
        int nt = idx >> 13, rem = idx & 8191;
        int r = rem >> 6, c = rem & 63;
        int o = nt * 128 + r;
        float v = 0.f;
        if (c < 32){
            int e = c >> 3, rr = c & 7;
            v = 0.1f * qb[((size_t)e * D_OUTF + o) * 8 + rr] * sf[(size_t)e * D_OUTF + o];
        }
        size_t tile = (size_t)nt * KTOT + 64;
        uint32_t off = swz128((uint32_t)(r * 128 + c * 2)) >> 1;
        gB[tile * B_TILE_ELEMS + off] = __float2half_rn(v);
    }
}

// ---------------- lora fixup: reduce partials, mask, pack into gA chunk 64 ----------------
__global__ void __launch_bounds__(256) lora_fixup_kernel(const float* __restrict__ tkw){
    int tid = threadIdx.x;
    int n0 = blockIdx.x * 64;
    int r = tid >> 2, e = tid & 3, jq = e * 8;
    int n = n0 + r;
    float w = tkw[n * 4 + e];
    w = (fabsf(w) > 1e-6f) ? w : 0.f;
    float s[8] = {0,0,0,0,0,0,0,0};
    #pragma unroll
    for (int p = 0; p < KSPLIT; p++){
        const float4* src = reinterpret_cast<const float4*>(g_part + ((size_t)p * N_TOK + n) * 32 + jq);
        float4 a = src[0], b = src[1];
        s[0] += a.x; s[1] += a.y; s[2] += a.z; s[3] += a.w;
        s[4] += b.x; s[5] += b.y; s[6] += b.z; s[7] += b.w;
    }
    uint4 h;
    h.x = pack2h(s[0]*w, s[1]*w); h.y = pack2h(s[2]*w, s[3]*w);
    h.z = pack2h(s[4]*w, s[5]*w); h.w = pack2h(s[6]*w, s[7]*w);
    int mt = n >> 7, rr = n & 127;
    size_t tile = (size_t)mt * KTOT + 64;
    char* tb = reinterpret_cast<char*>(&gA[tile * A_TILE_ELEMS]);
    *reinterpret_cast<uint4*>(tb + swz128((uint32_t)(rr * 128 + jq * 2))) = h;
    *reinterpret_cast<uint4*>(tb + swz128((uint32_t)(rr * 128 + (32 + jq) * 2))) = make_uint4(0,0,0,0);
}

// ---------------- main GEMM (known-best): warp-specialized producer, 3-stage ring ----------------
__global__ void __launch_bounds__(288, 2) gemm_hmma_kernel(float* __restrict__ out){
    extern __shared__ char smem_raw[];
    uint32_t raw = smem_u32(smem_raw);
    uint32_t sb  = (raw + 1023u) & ~1023u;        // barrier block
    uint32_t st0 = sb + 1024;                     // stage 0

    int tid = threadIdx.x, wid = tid >> 5, lane = tid & 31;
    int bid = blockIdx.x;
    int nt = bid >> 6, mt = bid & 63;             // panel raster: 64 M-tiles share B panel in L2

    const __half* pA = gA + (size_t)mt * (KTOT * A_TILE_ELEMS);
    const __half* pB = gB + (size_t)nt * (KTOT * B_TILE_ELEMS);

    // barriers: full[s] at sb + s*8, empty[s] at sb + 64 + s*8 (empty counts = 256 compute threads)
    if (tid == 0){
        #pragma unroll
        for (int s = 0; s < NSTAGE; s++){
            MBARRIER_INIT(sb + s * 8, 1);
            MBARRIER_INIT(sb + 64 + s * 8, 256);
        }
        asm volatile("fence.proxy.async.shared::cta;" ::: "memory");
    }
    __syncthreads();

    if (wid == 8){
        // ---- producer warp: one thread drives the whole TMA ring ----
        if (lane == 0){
            #pragma unroll
            for (int s = 0; s < NSTAGE; s++){
                uint32_t st = st0 + s * STAGE_BYTES;
                uint32_t mbf = sb + s * 8;
                MBARRIER_EXPECT_TX(mbf, STAGE_BYTES);
                bulk_g2s(st,                pA + (size_t)s * A_TILE_ELEMS, A_TILE_BYTES, mbf);
                bulk_g2s(st + A_TILE_BYTES, pB + (size_t)s * B_TILE_ELEMS, B_TILE_BYTES, mbf);
            }
            int s = 0, ph = 0;
            for (int c = NSTAGE; c < KTOT; c++){
                MBARRIER_WAIT_PARITY(sb + 64 + s * 8, ph);    // stage drained by consumers
                uint32_t st = st0 + s * STAGE_BYTES;
                uint32_t mbf = sb + s * 8;
                MBARRIER_EXPECT_TX(mbf, STAGE_BYTES);
                bulk_g2s(st,                pA + (size_t)c * A_TILE_ELEMS, A_TILE_BYTES, mbf);
                bulk_g2s(st + A_TILE_BYTES, pB + (size_t)c * B_TILE_ELEMS, B_TILE_BYTES, mbf);
                if (++s == NSTAGE){ s = 0; ph ^= 1; }
            }
        }
        return;
    }

    // ---- compute warps 0..7 (32x64 warp tiles) ----
    int warp_m = wid & 3, warp_n = wid >> 2;

    int lm = (lane >> 3) & 1;                     // row-half select within x4
    int lr = lane & 7;
    uint32_t g16 = (lane & 16);                   // k 16B-group select (0 or 16)
    uint32_t xm  = (uint32_t)(lr << 4);           // swizzle xor mask ((row&7)<<4)
    uint32_t aRow[2], bRow[4];
    #pragma unroll
    for (int mi = 0; mi < 2; mi++)
        aRow[mi] = (uint32_t)((warp_m * 32 + mi * 16 + lm * 8 + lr) * 128);
    #pragma unroll
    for (int nj = 0; nj < 4; nj++)
        bRow[nj] = (uint32_t)((warp_n * 64 + nj * 16 + lm * 8 + lr) * 128);

    float acc[2][8][4];
    #pragma unroll
    for (int mi = 0; mi < 2; mi++)
        #pragma unroll
        for (int ni = 0; ni < 8; ni++)
            #pragma unroll
            for (int q = 0; q < 4; q++) acc[mi][ni][q] = 0.f;

    int s = 0, ph = 0;
    for (int i = 0; i < KTOT; i++){
        MBARRIER_WAIT_PARITY(sb + s * 8, ph);

        uint32_t stg = st0 + s * STAGE_BYTES;
        uint32_t sA  = stg;
        uint32_t sB  = stg + A_TILE_BYTES;

        #pragma unroll
        for (int ks = 0; ks < 4; ks++){
            uint32_t koff = ((uint32_t)(ks * 32) + g16) ^ xm;
            uint32_t a[2][4], b[8][2];
            #pragma unroll
            for (int mi = 0; mi < 2; mi++)
                LDSM_X4(a[mi][0], a[mi][1], a[mi][2], a[mi][3], sA + aRow[mi] + koff);
            #pragma unroll
            for (int nj = 0; nj < 4; nj++){
                uint32_t t0, t1, t2, t3;
                LDSM_X4(t0, t1, t2, t3, sB + bRow[nj] + koff);
                b[2*nj][0] = t0; b[2*nj][1] = t2;
                b[2*nj+1][0] = t1; b[2*nj+1][1] = t3;
            }
            #pragma unroll
            for (int mi = 0; mi < 2; mi++)
                #pragma unroll
                for (int ni = 0; ni < 8; ni++)
                    MMA16816(acc[mi][ni], a[mi], b[ni]);
        }

        // arrive AFTER MMAs: MMA issue implies LDSM completion (register scoreboard),
        // so the producer can never overwrite a stage with reads in flight.
        MBARRIER_ARRIVE(sb + 64 + s * 8);
        if (++s == NSTAGE){ s = 0; ph ^= 1; }
    }

    // epilogue: direct STG.64 from accumulators
    int rowbase = mt * MT + warp_m * 32;
    int colbase = nt * NT + warp_n * 64;
    int rlo = lane >> 2, cq = (lane & 3) * 2;
    #pragma unroll
    for (int mi = 0; mi < 2; mi++){
        #pragma unroll
        for (int ni = 0; ni < 8; ni++){
            int r0 = rowbase + mi * 16 + rlo;
            int c  = colbase + ni * 8 + cq;
            float2 v0 = make_float2(acc[mi][ni][0], acc[mi][ni][1]);
            float2 v1 = make_float2(acc[mi][ni][2], acc[mi][ni][3]);
            *reinterpret_cast<float2*>(&out[(size_t)r0 * D_OUTF + c])       = v0;
            *reinterpret_cast<float2*>(&out[(size_t)(r0 + 8) * D_OUTF + c]) = v1;
        }
    }
}

// ---------------- launch ----------------
extern "C" void kernel_launch(void* const* d_in, const int* in_sizes, int n_in,
                              void* d_out, int out_size){
    const float* x   = (const float*)d_in[0];   // [8192, 4096]
    const float* tkw = (const float*)d_in[1];   // [8192, 4]
    const float* W   = (const float*)d_in[2];   // [4096, 4096]
    const float* qa  = (const float*)d_in[3];   // [4, 8, 4096]
    const float* qb  = (const float*)d_in[4];   // [4, 4096, 8]
    const float* sf  = (const float*)d_in[5];   // [4, 4096]
    float* out = (float*)d_out;                 // [8192, 4096]

    fused_prep_kernel<<<LBLK + XBLK + WBLK + PBLK, 256>>>(x, W, qb, sf, qa);
    lora_fixup_kernel<<<N_TOK / 64, 256>>>(tkw);

    cudaFuncSetAttribute(gemm_hmma_kernel,
                         cudaFuncAttributeMaxDynamicSharedMemorySize, SMEM_TOTAL);
    gemm_hmma_kernel<<<M_TILES * N_TILES, 288, SMEM_TOTAL>>>(out);
}

// round 16
// speedup vs baseline: 1.4297x; 1.4297x over previous
#include <cuda_runtime.h>
#include <cuda_fp16.h>
#include <cstdint>
#include <cstddef>

// ---------------- problem constants ----------------
#define N_TOK  8192
#define D_INF  4096
#define D_OUTF 4096

// GEMM tiling (known-best): CTA 128x128, warp 32x64 (4x2), BK=64, 3 stages, 2 CTA/SM
#define MT   128
#define NT   128
#define BK   64
#define M_TILES 64      // 8192/128
#define N_TILES 32      // 4096/128
#define KTOT    65      // 64 main K-chunks + 1 LoRA chunk
#define NSTAGE  3

#define A_TILE_ELEMS (MT*BK)        // 8192 halves (16 KB)
#define B_TILE_ELEMS (NT*BK)        // 8192 halves (16 KB)
#define A_TILE_BYTES (A_TILE_ELEMS*2)
#define B_TILE_BYTES (B_TILE_ELEMS*2)
#define STAGE_BYTES  (A_TILE_BYTES + B_TILE_BYTES)       // 32768
#define SMEM_TOTAL   (1024 + 1024 + NSTAGE*STAGE_BYTES)  // 100352 -> 2 CTAs/SM

#define KSPLIT 8

// ---------------- scratch (device globals; no cudaMalloc allowed) ----------------
__device__ __align__(1024) __half gA[(size_t)M_TILES*KTOT*A_TILE_ELEMS];  // x (fp16)
__device__ __align__(1024) __half gB[(size_t)N_TILES*KTOT*B_TILE_ELEMS];  // W (fp16)
__device__ __align__(1024) float g_part[(size_t)KSPLIT*N_TOK*32];         // lora partials

// ---------------- PTX helpers (sm_100 baseline only) ----------------
__device__ __forceinline__ uint32_t smem_u32(const void* p){
    uint32_t a;
    asm("{ .reg .u64 t; cvta.to.shared.u64 t, %1; cvt.u32.u64 %0, t; }" : "=r"(a) : "l"(p));
    return a;
}
__device__ __forceinline__ uint32_t swz128(uint32_t b){ return b ^ ((b >> 3) & 0x70); }

#define MBARRIER_INIT(addr, cnt) \
    asm volatile("mbarrier.init.shared.b64 [%0], %1;" :: "r"(addr), "r"(cnt) : "memory")
#define MBARRIER_EXPECT_TX(addr, bytes) \
    asm volatile("mbarrier.arrive.expect_tx.shared.b64 _, [%0], %1;" :: "r"(addr), "r"(bytes) : "memory")
#define MBARRIER_ARRIVE(addr) \
    asm volatile("mbarrier.arrive.shared.b64 _, [%0];" :: "r"(addr) : "memory")
#define MBARRIER_WAIT_PARITY(addr, par) do {                                     \
    uint32_t _m = (addr); uint32_t _p = (par); uint32_t _d;                      \
    asm volatile("{\n\t.reg .pred p;\n\t"                                        \
        "mbarrier.try_wait.parity.acquire.cta.shared::cta.b64 p, [%1], %2;\n\t"  \
        "selp.b32 %0, 1, 0, p;\n\t}" : "=r"(_d) : "r"(_m), "r"(_p) : "memory");  \
    if (!_d) {                                                                   \
        asm volatile("{\n\t.reg .pred P1;\n\t"                                   \
        "W_%=:\n\t"                                                              \
        "mbarrier.try_wait.parity.acquire.cta.shared::cta.b64 P1, [%0], %1, 0x989680;\n\t" \
        "@P1 bra.uni D_%=;\n\t"                                                  \
        "bra.uni W_%=;\n\t"                                                      \
        "D_%=:\n\t}" :: "r"(_m), "r"(_p) : "memory");                            \
    }                                                                            \
} while (0)

__device__ __forceinline__ void bulk_g2s(uint32_t dst, const void* src, uint32_t bytes, uint32_t mbar){
    asm volatile("cp.async.bulk.shared::cta.global.mbarrier::complete_tx::bytes [%0], [%1], %2, [%3];"
        :: "r"(dst), "l"(src), "r"(bytes), "r"(mbar) : "memory");
}

#define LDSM_X4(r0, r1, r2, r3, addr) \
    asm volatile("ldmatrix.sync.aligned.m8n8.x4.shared.b16 {%0,%1,%2,%3}, [%4];" \
        : "=r"(r0), "=r"(r1), "=r"(r2), "=r"(r3) : "r"(addr))

#define MMA16816(d, a, b) \
    asm volatile("mma.sync.aligned.m16n8k16.row.col.f32.f16.f16.f32 " \
        "{%0,%1,%2,%3}, {%4,%5,%6,%7}, {%8,%9}, {%0,%1,%2,%3};" \
        : "+f"((d)[0]), "+f"((d)[1]), "+f"((d)[2]), "+f"((d)[3]) \
        : "r"((a)[0]), "r"((a)[1]), "r"((a)[2]), "r"((a)[3]), "r"((b)[0]), "r"((b)[1]))

__device__ __forceinline__ uint32_t pack2h(float a, float b){
    __half2 h = __floats2half2_rn(a, b);
    return *reinterpret_cast<uint32_t*>(&h);
}

// ---------------- fused prep: lora split-K partials | x conv | W conv | LoRA-B chunk ----------------
#define LBLK 1024       // 128 token-groups x 8 k-splits
#define XBLK 16384      // (8192*4096/8)/256
#define WBLK 8192       // (4096*4096/8)/256
#define PBLK 1024       // (32*8192)/256

// conflict-free float4 row layout: 36-float stride + per-8-row 8-float (32B) quadrant shift.
// rows 8 apart land at byte offsets 0/32/64/96 mod 128 -> the 4 expert lanes of a quad
// read distinct bank quadrants (the 1152B-stride 4-way conflict of LSTR=36 is broken).
__device__ __forceinline__ int lrow(int row){ return row * 36 + ((row >> 3) & 3) * 8; }

__global__ void __launch_bounds__(256) fused_prep_kernel(const float* __restrict__ x,
                                                         const float* __restrict__ W,
                                                         const float* __restrict__ qb,
                                                         const float* __restrict__ sf,
                                                         const float* __restrict__ qa){
    int bid = blockIdx.x, tid = threadIdx.x;
    if (bid < LBLK){
        // ---- LoRA split-K partial: 64 tokens x 512-k slice -> g_part[p][n][j] ----
        __shared__ float sqa[32*36 + 32];
        __shared__ float sx[64*36 + 32];
        int n0 = (bid >> 3) * 64;
        int p  = bid & 7;
        int kbase = p * (D_INF / KSPLIT);           // 512-wide slice
        int r   = tid >> 2;            // token row 0..63
        int e   = tid & 3;             // expert
        int jq  = e * 8;
        float acc[8] = {0,0,0,0,0,0,0,0};
        for (int k0 = kbase; k0 < kbase + D_INF / KSPLIT; k0 += 32){
            // fill smem as float4s (rows 16B-aligned; lrow keeps 16B alignment)
            {
                int i = tid;                         // 256 float4 = whole sqa tile
                int row = i >> 3, c4 = i & 7;
                *reinterpret_cast<float4*>(&sqa[lrow(row) + c4 * 4]) =
                    *reinterpret_cast<const float4*>(&qa[(size_t)row * D_INF + k0 + c4 * 4]);
            }
            #pragma unroll
            for (int v = 0; v < 2; v++){
                int i = v * 256 + tid;               // 512 float4 = whole sx tile
                int row = i >> 3, c4 = i & 7;
                *reinterpret_cast<float4*>(&sx[lrow(row) + c4 * 4]) =
                    *reinterpret_cast<const float4*>(&x[(size_t)(n0 + row) * D_INF + k0 + c4 * 4]);
            }
            __syncthreads();
            int xoff = lrow(r), qoff = lrow(jq);    // note: rows jq..jq+7 share the same quad shift
            #pragma unroll
            for (int kk4 = 0; kk4 < 8; kk4++){
                float4 xv = *reinterpret_cast<const float4*>(&sx[xoff + kk4 * 4]);
                #pragma unroll
                for (int q = 0; q < 8; q++){
                    float4 qv = *reinterpret_cast<const float4*>(&sqa[qoff + q * 36 + kk4 * 4]);
                    // EXACT same k-order accumulation as the scalar version
                    acc[q] = fmaf(xv.x, qv.x, acc[q]);
                    acc[q] = fmaf(xv.y, qv.y, acc[q]);
                    acc[q] = fmaf(xv.z, qv.z, acc[q]);
                    acc[q] = fmaf(xv.w, qv.w, acc[q]);
                }
            }
            __syncthreads();
        }
        int n = n0 + r;
        float4* dst = reinterpret_cast<float4*>(g_part + ((size_t)p * N_TOK + n) * 32 + jq);
        dst[0] = make_float4(acc[0], acc[1], acc[2], acc[3]);
        dst[1] = make_float4(acc[4], acc[5], acc[6], acc[7]);
    } else if (bid < LBLK + XBLK){
        size_t t = (size_t)(bid - LBLK) * 256 + tid;
        size_t base = t * 8;                              // k%8==0
        int n = (int)(base >> 12), k = (int)(base & 4095);
        float4 v0 = *reinterpret_cast<const float4*>(x + base);
        float4 v1 = *reinterpret_cast<const float4*>(x + base + 4);
        uint4 h;
        h.x = pack2h(v0.x, v0.y); h.y = pack2h(v0.z, v0.w);
        h.z = pack2h(v1.x, v1.y); h.w = pack2h(v1.z, v1.w);
        int mt = n >> 7, r = n & 127, kc = k >> 6, c = k & 63;
        size_t tile = (size_t)mt * KTOT + kc;
        uint32_t off = swz128((uint32_t)(r * 128 + c * 2));   // 16B-aligned -> stays aligned
        *reinterpret_cast<uint4*>(reinterpret_cast<char*>(&gA[tile * A_TILE_ELEMS]) + off) = h;
    } else if (bid < LBLK + XBLK + WBLK){
        size_t t = (size_t)(bid - LBLK - XBLK) * 256 + tid;
        size_t base = t * 8;
        int o = (int)(base >> 12), k = (int)(base & 4095);
        float4 v0 = *reinterpret_cast<const float4*>(W + base);
        float4 v1 = *reinterpret_cast<const float4*>(W + base + 4);
        uint4 h;
        h.x = pack2h(v0.x, v0.y); h.y = pack2h(v0.z, v0.w);
        h.z = pack2h(v1.x, v1.y); h.w = pack2h(v1.z, v1.w);
        int nt = o >> 7, r = o & 127, kc = k >> 6, c = k & 63;
        size_t tile = (size_t)nt * KTOT + kc;
        uint32_t off = swz128((uint32_t)(r * 128 + c * 2));
        *reinterpret_cast<uint4*>(reinterpret_cast<char*>(&gB[tile * B_TILE_ELEMS]) + off) = h;
    } else {
        int idx = (bid - LBLK - XBLK - WBLK) * 256 + tid; // < 32*8192
        int nt = idx >> 13, rem = idx & 8191;
        int r = rem >> 6, c = rem & 63;
        int o = nt * 128 + r;
        float v = 0.f;
        if (c < 32){
            int e = c >> 3, rr = c & 7;
            v = 0.1f * qb[((size_t)e * D_OUTF + o) * 8 + rr] * sf[(size_t)e * D_OUTF + o];
        }
        size_t tile = (size_t)nt * KTOT + 64;
        uint32_t off = swz128((uint32_t)(r * 128 + c * 2)) >> 1;
        gB[tile * B_TILE_ELEMS + off] = __float2half_rn(v);
    }
}

// ---------------- lora fixup: reduce partials, mask, pack into gA chunk 64 ----------------
__global__ void __launch_bounds__(256) lora_fixup_kernel(const float* __restrict__ tkw){
    int tid = threadIdx.x;
    int n0 = blockIdx.x * 64;
    int r = tid >> 2, e = tid & 3, jq = e * 8;
    int n = n0 + r;
    float w = tkw[n * 4 + e];
    w = (fabsf(w) > 1e-6f) ? w : 0.f;
    float s[8] = {0,0,0,0,0,0,0,0};
    #pragma unroll
    for (int p = 0; p < KSPLIT; p++){
        const float4* src = reinterpret_cast<const float4*>(g_part + ((size_t)p * N_TOK + n) * 32 + jq);
        float4 a = src[0], b = src[1];
        s[0] += a.x; s[1] += a.y; s[2] += a.z; s[3] += a.w;
        s[4] += b.x; s[5] += b.y; s[6] += b.z; s[7] += b.w;
    }
    uint4 h;
    h.x = pack2h(s[0]*w, s[1]*w); h.y = pack2h(s[2]*w, s[3]*w);
    h.z = pack2h(s[4]*w, s[5]*w); h.w = pack2h(s[6]*w, s[7]*w);
    int mt = n >> 7, rr = n & 127;
    size_t tile = (size_t)mt * KTOT + 64;
    char* tb = reinterpret_cast<char*>(&gA[tile * A_TILE_ELEMS]);
    *reinterpret_cast<uint4*>(tb + swz128((uint32_t)(rr * 128 + jq * 2))) = h;
    *reinterpret_cast<uint4*>(tb + swz128((uint32_t)(rr * 128 + (32 + jq) * 2))) = make_uint4(0,0,0,0);
}

// ---------------- main GEMM (known-best): warp-specialized producer, 3-stage ring ----------------
__global__ void __launch_bounds__(288, 2) gemm_hmma_kernel(float* __restrict__ out){
    extern __shared__ char smem_raw[];
    uint32_t raw = smem_u32(smem_raw);
    uint32_t sb  = (raw + 1023u) & ~1023u;        // barrier block
    uint32_t st0 = sb + 1024;                     // stage 0

    int tid = threadIdx.x, wid = tid >> 5, lane = tid & 31;
    int bid = blockIdx.x;
    int nt = bid >> 6, mt = bid & 63;             // panel raster: 64 M-tiles share B panel in L2

    const __half* pA = gA + (size_t)mt * (KTOT * A_TILE_ELEMS);
    const __half* pB = gB + (size_t)nt * (KTOT * B_TILE_ELEMS);

    // barriers: full[s] at sb + s*8, empty[s] at sb + 64 + s*8 (empty counts = 256 compute threads)
    if (tid == 0){
        #pragma unroll
        for (int s = 0; s < NSTAGE; s++){
            MBARRIER_INIT(sb + s * 8, 1);
            MBARRIER_INIT(sb + 64 + s * 8, 256);
        }
        asm volatile("fence.proxy.async.shared::cta;" ::: "memory");
    }
    __syncthreads();

    if (wid == 8){
        // ---- producer warp: one thread drives the whole TMA ring ----
        if (lane == 0){
            #pragma unroll
            for (int s = 0; s < NSTAGE; s++){
                uint32_t st = st0 + s * STAGE_BYTES;
                uint32_t mbf = sb + s * 8;
                MBARRIER_EXPECT_TX(mbf, STAGE_BYTES);
                bulk_g2s(st,                pA + (size_t)s * A_TILE_ELEMS, A_TILE_BYTES, mbf);
                bulk_g2s(st + A_TILE_BYTES, pB + (size_t)s * B_TILE_ELEMS, B_TILE_BYTES, mbf);
            }
            int s = 0, ph = 0;
            for (int c = NSTAGE; c < KTOT; c++){
                MBARRIER_WAIT_PARITY(sb + 64 + s * 8, ph);    // stage drained by consumers
                uint32_t st = st0 + s * STAGE_BYTES;
                uint32_t mbf = sb + s * 8;
                MBARRIER_EXPECT_TX(mbf, STAGE_BYTES);
                bulk_g2s(st,                pA + (size_t)c * A_TILE_ELEMS, A_TILE_BYTES, mbf);
                bulk_g2s(st + A_TILE_BYTES, pB + (size_t)c * B_TILE_ELEMS, B_TILE_BYTES, mbf);
                if (++s == NSTAGE){ s = 0; ph ^= 1; }
            }
        }
        return;
    }

    // ---- compute warps 0..7 (32x64 warp tiles) ----
    int warp_m = wid & 3, warp_n = wid >> 2;

    int lm = (lane >> 3) & 1;                     // row-half select within x4
    int lr = lane & 7;
    uint32_t g16 = (lane & 16);                   // k 16B-group select (0 or 16)
    uint32_t xm  = (uint32_t)(lr << 4);           // swizzle xor mask ((row&7)<<4)
    uint32_t aRow[2], bRow[4];
    #pragma unroll
    for (int mi = 0; mi < 2; mi++)
        aRow[mi] = (uint32_t)((warp_m * 32 + mi * 16 + lm * 8 + lr) * 128);
    #pragma unroll
    for (int nj = 0; nj < 4; nj++)
        bRow[nj] = (uint32_t)((warp_n * 64 + nj * 16 + lm * 8 + lr) * 128);

    float acc[2][8][4];
    #pragma unroll
    for (int mi = 0; mi < 2; mi++)
        #pragma unroll
        for (int ni = 0; ni < 8; ni++)
            #pragma unroll
            for (int q = 0; q < 4; q++) acc[mi][ni][q] = 0.f;

    int s = 0, ph = 0;
    for (int i = 0; i < KTOT; i++){
        MBARRIER_WAIT_PARITY(sb + s * 8, ph);

        uint32_t stg = st0 + s * STAGE_BYTES;
        uint32_t sA  = stg;
        uint32_t sB  = stg + A_TILE_BYTES;

        #pragma unroll
        for (int ks = 0; ks < 4; ks++){
            uint32_t koff = ((uint32_t)(ks * 32) + g16) ^ xm;
            uint32_t a[2][4], b[8][2];
            #pragma unroll
            for (int mi = 0; mi < 2; mi++)
                LDSM_X4(a[mi][0], a[mi][1], a[mi][2], a[mi][3], sA + aRow[mi] + koff);
            #pragma unroll
            for (int nj = 0; nj < 4; nj++){
                uint32_t t0, t1, t2, t3;
                LDSM_X4(t0, t1, t2, t3, sB + bRow[nj] + koff);
                b[2*nj][0] = t0; b[2*nj][1] = t2;
                b[2*nj+1][0] = t1; b[2*nj+1][1] = t3;
            }
            #pragma unroll
            for (int mi = 0; mi < 2; mi++)
                #pragma unroll
                for (int ni = 0; ni < 8; ni++)
                    MMA16816(acc[mi][ni], a[mi], b[ni]);
        }

        // arrive AFTER MMAs: MMA issue implies LDSM completion (register scoreboard),
        // so the producer can never overwrite a stage with reads in flight.
        MBARRIER_ARRIVE(sb + 64 + s * 8);
        if (++s == NSTAGE){ s = 0; ph ^= 1; }
    }

    // epilogue: direct STG.64 from accumulators
    int rowbase = mt * MT + warp_m * 32;
    int colbase = nt * NT + warp_n * 64;
    int rlo = lane >> 2, cq = (lane & 3) * 2;
    #pragma unroll
    for (int mi = 0; mi < 2; mi++){
        #pragma unroll
        for (int ni = 0; ni < 8; ni++){
            int r0 = rowbase + mi * 16 + rlo;
            int c  = colbase + ni * 8 + cq;
            float2 v0 = make_float2(acc[mi][ni][0], acc[mi][ni][1]);
            float2 v1 = make_float2(acc[mi][ni][2], acc[mi][ni][3]);
            *reinterpret_cast<float2*>(&out[(size_t)r0 * D_OUTF + c])       = v0;
            *reinterpret_cast<float2*>(&out[(size_t)(r0 + 8) * D_OUTF + c]) = v1;
        }
    }
}

// ---------------- launch ----------------
extern "C" void kernel_launch(void* const* d_in, const int* in_sizes, int n_in,
                              void* d_out, int out_size){
    const float* x   = (const float*)d_in[0];   // [8192, 4096]
    const float* tkw = (const float*)d_in[1];   // [8192, 4]
    const float* W   = (const float*)d_in[2];   // [4096, 4096]
    const float* qa  = (const float*)d_in[3];   // [4, 8, 4096]
    const float* qb  = (const float*)d_in[4];   // [4, 4096, 8]
    const float* sf  = (const float*)d_in[5];   // [4, 4096]
    float* out = (float*)d_out;                 // [8192, 4096]

    fused_prep_kernel<<<LBLK + XBLK + WBLK + PBLK, 256>>>(x, W, qb, sf, qa);
    lora_fixup_kernel<<<N_TOK / 64, 256>>>(tkw);

    cudaFuncSetAttribute(gemm_hmma_kernel,
                         cudaFuncAttributeMaxDynamicSharedMemorySize, SMEM_TOTAL);
    gemm_hmma_kernel<<<M_TILES * N_TILES, 288, SMEM_TOTAL>>>(out);
}

// round 17
// speedup vs baseline: 1.4444x; 1.0103x over previous
#include <cuda_runtime.h>
#include <cuda_fp16.h>
#include <cstdint>
#include <cstddef>

// ---------------- problem constants ----------------
#define N_TOK  8192
#define D_INF  4096
#define D_OUTF 4096

// GEMM tiling (known-best): CTA 128x128, warp 32x64 (4x2), BK=64, 3 stages, 2 CTA/SM
#define MT   128
#define NT   128
#define BK   64
#define M_TILES 64      // 8192/128
#define N_TILES 32      // 4096/128
#define KTOT    65      // 64 main K-chunks + 1 LoRA chunk
#define NSTAGE  3

#define A_TILE_ELEMS (MT*BK)        // 8192 halves (16 KB)
#define B_TILE_ELEMS (NT*BK)        // 8192 halves (16 KB)
#define A_TILE_BYTES (A_TILE_ELEMS*2)
#define B_TILE_BYTES (B_TILE_ELEMS*2)
#define STAGE_BYTES  (A_TILE_BYTES + B_TILE_BYTES)       // 32768
#define SMEM_TOTAL   (1024 + 1024 + NSTAGE*STAGE_BYTES)  // 100352 -> 2 CTAs/SM

#define KSPLIT 8

// ---------------- scratch (device globals; no cudaMalloc allowed) ----------------
__device__ __align__(1024) __half gA[(size_t)M_TILES*KTOT*A_TILE_ELEMS];  // x (fp16)
__device__ __align__(1024) __half gB[(size_t)N_TILES*KTOT*B_TILE_ELEMS];  // W (fp16)
__device__ __align__(1024) float g_part[(size_t)KSPLIT*N_TOK*32];         // lora partials

// ---------------- PTX helpers (sm_100 baseline only) ----------------
__device__ __forceinline__ uint32_t smem_u32(const void* p){
    uint32_t a;
    asm("{ .reg .u64 t; cvta.to.shared.u64 t, %1; cvt.u32.u64 %0, t; }" : "=r"(a) : "l"(p));
    return a;
}
__device__ __forceinline__ uint32_t swz128(uint32_t b){ return b ^ ((b >> 3) & 0x70); }

#define MBARRIER_INIT(addr, cnt) \
    asm volatile("mbarrier.init.shared.b64 [%0], %1;" :: "r"(addr), "r"(cnt) : "memory")
#define MBARRIER_EXPECT_TX(addr, bytes) \
    asm volatile("mbarrier.arrive.expect_tx.shared.b64 _, [%0], %1;" :: "r"(addr), "r"(bytes) : "memory")
#define MBARRIER_ARRIVE(addr) \
    asm volatile("mbarrier.arrive.shared.b64 _, [%0];" :: "r"(addr) : "memory")
#define MBARRIER_WAIT_PARITY(addr, par) do {                                     \
    uint32_t _m = (addr); uint32_t _p = (par); uint32_t _d;                      \
    asm volatile("{\n\t.reg .pred p;\n\t"                                        \
        "mbarrier.try_wait.parity.acquire.cta.shared::cta.b64 p, [%1], %2;\n\t"  \
        "selp.b32 %0, 1, 0, p;\n\t}" : "=r"(_d) : "r"(_m), "r"(_p) : "memory");  \
    if (!_d) {                                                                   \
        asm volatile("{\n\t.reg .pred P1;\n\t"                                   \
        "W_%=:\n\t"                                                              \
        "mbarrier.try_wait.parity.acquire.cta.shared::cta.b64 P1, [%0], %1, 0x989680;\n\t" \
        "@P1 bra.uni D_%=;\n\t"                                                  \
        "bra.uni W_%=;\n\t"                                                      \
        "D_%=:\n\t}" :: "r"(_m), "r"(_p) : "memory");                            \
    }                                                                            \
} while (0)

__device__ __forceinline__ void bulk_g2s(uint32_t dst, const void* src, uint32_t bytes, uint32_t mbar){
    asm volatile("cp.async.bulk.shared::cta.global.mbarrier::complete_tx::bytes [%0], [%1], %2, [%3];"
        :: "r"(dst), "l"(src), "r"(bytes), "r"(mbar) : "memory");
}

#define LDSM_X4(r0, r1, r2, r3, addr) \
    asm volatile("ldmatrix.sync.aligned.m8n8.x4.shared.b16 {%0,%1,%2,%3}, [%4];" \
        : "=r"(r0), "=r"(r1), "=r"(r2), "=r"(r3) : "r"(addr))

#define MMA16816(d, a, b) \
    asm volatile("mma.sync.aligned.m16n8k16.row.col.f32.f16.f16.f32 " \
        "{%0,%1,%2,%3}, {%4,%5,%6,%7}, {%8,%9}, {%0,%1,%2,%3};" \
        : "+f"((d)[0]), "+f"((d)[1]), "+f"((d)[2]), "+f"((d)[3]) \
        : "r"((a)[0]), "r"((a)[1]), "r"((a)[2]), "r"((a)[3]), "r"((b)[0]), "r"((b)[1]))

__device__ __forceinline__ uint32_t pack2h(float a, float b){
    __half2 h = __floats2half2_rn(a, b);
    return *reinterpret_cast<uint32_t*>(&h);
}

// ---------------- fused prep: lora split-K partials | x conv | W conv | LoRA-B chunk ----------------
#define LBLK 1024       // 128 token-groups x 8 k-splits
#define XBLK 16384      // (8192*4096/8)/256
#define WBLK 8192       // (4096*4096/8)/256
#define PBLK 1024       // (32*8192)/256

// conflict-free float4 row layout: 36-float stride + per-8-row 8-float (32B) quadrant shift.
// rows 8 apart land at byte offsets 0/32/64/96 mod 128 -> the 4 expert lanes of a quad
// read distinct bank quadrants (the 1152B-stride 4-way conflict of LSTR=36 is broken).
__device__ __forceinline__ int lrow(int row){ return row * 36 + ((row >> 3) & 3) * 8; }

__global__ void __launch_bounds__(256) fused_prep_kernel(const float* __restrict__ x,
                                                         const float* __restrict__ W,
                                                         const float* __restrict__ qb,
                                                         const float* __restrict__ sf,
                                                         const float* __restrict__ qa){
    int bid = blockIdx.x, tid = threadIdx.x;
    if (bid < LBLK){
        // ---- LoRA split-K partial: 64 tokens x 512-k slice -> g_part[p][n][j] ----
        __shared__ float sqa[32*36 + 32];
        __shared__ float sx[64*36 + 32];
        int n0 = (bid >> 3) * 64;
        int p  = bid & 7;
        int kbase = p * (D_INF / KSPLIT);           // 512-wide slice
        int r   = tid >> 2;            // token row 0..63
        int e   = tid & 3;             // expert
        int jq  = e * 8;
        float acc[8] = {0,0,0,0,0,0,0,0};
        for (int k0 = kbase; k0 < kbase + D_INF / KSPLIT; k0 += 32){
            // fill smem as float4s (rows 16B-aligned; lrow keeps 16B alignment)
            {
                int i = tid;                         // 256 float4 = whole sqa tile
                int row = i >> 3, c4 = i & 7;
                *reinterpret_cast<float4*>(&sqa[lrow(row) + c4 * 4]) =
                    *reinterpret_cast<const float4*>(&qa[(size_t)row * D_INF + k0 + c4 * 4]);
            }
            #pragma unroll
            for (int v = 0; v < 2; v++){
                int i = v * 256 + tid;               // 512 float4 = whole sx tile
                int row = i >> 3, c4 = i & 7;
                *reinterpret_cast<float4*>(&sx[lrow(row) + c4 * 4]) =
                    *reinterpret_cast<const float4*>(&x[(size_t)(n0 + row) * D_INF + k0 + c4 * 4]);
            }
            __syncthreads();
            int xoff = lrow(r), qoff = lrow(jq);    // note: rows jq..jq+7 share the same quad shift
            #pragma unroll
            for (int kk4 = 0; kk4 < 8; kk4++){
                float4 xv = *reinterpret_cast<const float4*>(&sx[xoff + kk4 * 4]);
                #pragma unroll
                for (int q = 0; q < 8; q++){
                    float4 qv = *reinterpret_cast<const float4*>(&sqa[qoff + q * 36 + kk4 * 4]);
                    // EXACT same k-order accumulation as the scalar version
                    acc[q] = fmaf(xv.x, qv.x, acc[q]);
                    acc[q] = fmaf(xv.y, qv.y, acc[q]);
                    acc[q] = fmaf(xv.z, qv.z, acc[q]);
                    acc[q] = fmaf(xv.w, qv.w, acc[q]);
                }
            }
            __syncthreads();
        }
        int n = n0 + r;
        float4* dst = reinterpret_cast<float4*>(g_part + ((size_t)p * N_TOK + n) * 32 + jq);
        dst[0] = make_float4(acc[0], acc[1], acc[2], acc[3]);
        dst[1] = make_float4(acc[4], acc[5], acc[6], acc[7]);
    } else if (bid < LBLK + XBLK){
        size_t t = (size_t)(bid - LBLK) * 256 + tid;
        size_t base = t * 8;                              // k%8==0
        int n = (int)(base >> 12), k = (int)(base & 4095);
        float4 v0 = *reinterpret_cast<const float4*>(x + base);
        float4 v1 = *reinterpret_cast<const float4*>(x + base + 4);
        uint4 h;
        h.x = pack2h(v0.x, v0.y); h.y = pack2h(v0.z, v0.w);
        h.z = pack2h(v1.x, v1.y); h.w = pack2h(v1.z, v1.w);
        int mt = n >> 7, r = n & 127, kc = k >> 6, c = k & 63;
        size_t tile = (size_t)mt * KTOT + kc;
        uint32_t off = swz128((uint32_t)(r * 128 + c * 2));   // 16B-aligned -> stays aligned
        *reinterpret_cast<uint4*>(reinterpret_cast<char*>(&gA[tile * A_TILE_ELEMS]) + off) = h;
    } else if (bid < LBLK + XBLK + WBLK){
        size_t t = (size_t)(bid - LBLK - XBLK) * 256 + tid;
        size_t base = t * 8;
        int o = (int)(base >> 12), k = (int)(base & 4095);
        float4 v0 = *reinterpret_cast<const float4*>(W + base);
        float4 v1 = *reinterpret_cast<const float4*>(W + base + 4);
        uint4 h;
        h.x = pack2h(v0.x, v0.y); h.y = pack2h(v0.z, v0.w);
        h.z = pack2h(v1.x, v1.y); h.w = pack2h(v1.z, v1.w);
        int nt = o >> 7, r = o & 127, kc = k >> 6, c = k & 63;
        size_t tile = (size_t)nt * KTOT + kc;
        uint32_t off = swz128((uint32_t)(r * 128 + c * 2));
        *reinterpret_cast<uint4*>(reinterpret_cast<char*>(&gB[tile * B_TILE_ELEMS]) + off) = h;
    } else {
        int idx = (bid - LBLK - XBLK - WBLK) * 256 + tid; // < 32*8192
        int nt = idx >> 13, rem = idx & 8191;
        int r = rem >> 6, c = rem & 63;
        int o = nt * 128 + r;
        float v = 0.f;
        if (c < 32){
            int e = c >> 3, rr = c & 7;
            v = 0.1f * qb[((size_t)e * D_OUTF + o) * 8 + rr] * sf[(size_t)e * D_OUTF + o];
        }
        size_t tile = (size_t)nt * KTOT + 64;
        uint32_t off = swz128((uint32_t)(r * 128 + c * 2)) >> 1;
        gB[tile * B_TILE_ELEMS + off] = __float2half_rn(v);
    }
}

// ---------------- lora fixup: reduce partials, mask, pack into gA chunk 64 ----------------
__global__ void __launch_bounds__(256) lora_fixup_kernel(const float* __restrict__ tkw){
    int tid = threadIdx.x;
    int n0 = blockIdx.x * 64;
    int r = tid >> 2, e = tid & 3, jq = e * 8;
    int n = n0 + r;
    float w = tkw[n * 4 + e];
    w = (fabsf(w) > 1e-6f) ? w : 0.f;
    float s[8] = {0,0,0,0,0,0,0,0};
    #pragma unroll
    for (int p = 0; p < KSPLIT; p++){
        const float4* src = reinterpret_cast<const float4*>(g_part + ((size_t)p * N_TOK + n) * 32 + jq);
        float4 a = src[0], b = src[1];
        s[0] += a.x; s[1] += a.y; s[2] += a.z; s[3] += a.w;
        s[4] += b.x; s[5] += b.y; s[6] += b.z; s[7] += b.w;
    }
    uint4 h;
    h.x = pack2h(s[0]*w, s[1]*w); h.y = pack2h(s[2]*w, s[3]*w);
    h.z = pack2h(s[4]*w, s[5]*w); h.w = pack2h(s[6]*w, s[7]*w);
    int mt = n >> 7, rr = n & 127;
    size_t tile = (size_t)mt * KTOT + 64;
    char* tb = reinterpret_cast<char*>(&gA[tile * A_TILE_ELEMS]);
    *reinterpret_cast<uint4*>(tb + swz128((uint32_t)(rr * 128 + jq * 2))) = h;
    *reinterpret_cast<uint4*>(tb + swz128((uint32_t)(rr * 128 + (32 + jq) * 2))) = make_uint4(0,0,0,0);
}

// ---------------- main GEMM (known-best): warp-specialized producer, 3-stage ring ----------------
__global__ void __launch_bounds__(288, 2) gemm_hmma_kernel(float* __restrict__ out){
    extern __shared__ char smem_raw[];
    uint32_t raw = smem_u32(smem_raw);
    uint32_t sb  = (raw + 1023u) & ~1023u;        // barrier block
    uint32_t st0 = sb + 1024;                     // stage 0

    int tid = threadIdx.x, wid = tid >> 5, lane = tid & 31;
    int bid = blockIdx.x;
    int nt = bid >> 6, mt = bid & 63;             // panel raster: 64 M-tiles share B panel in L2

    const __half* pA = gA + (size_t)mt * (KTOT * A_TILE_ELEMS);
    const __half* pB = gB + (size_t)nt * (KTOT * B_TILE_ELEMS);

    // barriers: full[s] at sb + s*8, empty[s] at sb + 64 + s*8 (empty counts = 256 compute threads)
    if (tid == 0){
        #pragma unroll
        for (int s = 0; s < NSTAGE; s++){
            MBARRIER_INIT(sb + s * 8, 1);
            MBARRIER_INIT(sb + 64 + s * 8, 256);
        }
        asm volatile("fence.proxy.async.shared::cta;" ::: "memory");
    }
    __syncthreads();

    if (wid == 8){
        // ---- producer warp: one thread drives the whole TMA ring ----
        if (lane == 0){
            #pragma unroll
            for (int s = 0; s < NSTAGE; s++){
                uint32_t st = st0 + s * STAGE_BYTES;
                uint32_t mbf = sb + s * 8;
                MBARRIER_EXPECT_TX(mbf, STAGE_BYTES);
                bulk_g2s(st,                pA + (size_t)s * A_TILE_ELEMS, A_TILE_BYTES, mbf);
                bulk_g2s(st + A_TILE_BYTES, pB + (size_t)s * B_TILE_ELEMS, B_TILE_BYTES, mbf);
            }
            int s = 0, ph = 0;
            for (int c = NSTAGE; c < KTOT; c++){
                MBARRIER_WAIT_PARITY(sb + 64 + s * 8, ph);    // stage drained by consumers
                uint32_t st = st0 + s * STAGE_BYTES;
                uint32_t mbf = sb + s * 8;
                MBARRIER_EXPECT_TX(mbf, STAGE_BYTES);
                bulk_g2s(st,                pA + (size_t)c * A_TILE_ELEMS, A_TILE_BYTES, mbf);
                bulk_g2s(st + A_TILE_BYTES, pB + (size_t)c * B_TILE_ELEMS, B_TILE_BYTES, mbf);
                if (++s == NSTAGE){ s = 0; ph ^= 1; }
            }
        }
        return;
    }

    // ---- compute warps 0..7 (32x64 warp tiles) ----
    int warp_m = wid & 3, warp_n = wid >> 2;

    int lm = (lane >> 3) & 1;                     // row-half select within x4
    int lr = lane & 7;
    uint32_t g16 = (lane & 16);                   // k 16B-group select (0 or 16)
    uint32_t xm  = (uint32_t)(lr << 4);           // swizzle xor mask ((row&7)<<4)
    uint32_t aRow[2], bRow[4];
    #pragma unroll
    for (int mi = 0; mi < 2; mi++)
        aRow[mi] = (uint32_t)((warp_m * 32 + mi * 16 + lm * 8 + lr) * 128);
    #pragma unroll
    for (int nj = 0; nj < 4; nj++)
        bRow[nj] = (uint32_t)((warp_n * 64 + nj * 16 + lm * 8 + lr) * 128);

    float acc[2][8][4];
    #pragma unroll
    for (int mi = 0; mi < 2; mi++)
        #pragma unroll
        for (int ni = 0; ni < 8; ni++)
            #pragma unroll
            for (int q = 0; q < 4; q++) acc[mi][ni][q] = 0.f;

    int s = 0, ph = 0;
    for (int i = 0; i < KTOT; i++){
        MBARRIER_WAIT_PARITY(sb + s * 8, ph);

        uint32_t stg = st0 + s * STAGE_BYTES;
        uint32_t sA  = stg;
        uint32_t sB  = stg + A_TILE_BYTES;

        #pragma unroll
        for (int ks = 0; ks < 4; ks++){
            uint32_t koff = ((uint32_t)(ks * 32) + g16) ^ xm;
            uint32_t a[2][4], b[8][2];
            #pragma unroll
            for (int mi = 0; mi < 2; mi++)
                LDSM_X4(a[mi][0], a[mi][1], a[mi][2], a[mi][3], sA + aRow[mi] + koff);
            #pragma unroll
            for (int nj = 0; nj < 4; nj++){
                uint32_t t0, t1, t2, t3;
                LDSM_X4(t0, t1, t2, t3, sB + bRow[nj] + koff);
                b[2*nj][0] = t0; b[2*nj][1] = t2;
                b[2*nj+1][0] = t1; b[2*nj+1][1] = t3;
            }
            #pragma unroll
            for (int mi = 0; mi < 2; mi++)
                #pragma unroll
                for (int ni = 0; ni < 8; ni++)
                    MMA16816(acc[mi][ni], a[mi], b[ni]);
        }

        // arrive AFTER MMAs: MMA issue implies LDSM completion (register scoreboard),
        // so the producer can never overwrite a stage with reads in flight.
        MBARRIER_ARRIVE(sb + 64 + s * 8);
        if (++s == NSTAGE){ s = 0; ph ^= 1; }
    }

    // epilogue: direct STG.64 from accumulators
    int rowbase = mt * MT + warp_m * 32;
    int colbase = nt * NT + warp_n * 64;
    int rlo = lane >> 2, cq = (lane & 3) * 2;
    #pragma unroll
    for (int mi = 0; mi < 2; mi++){
        #pragma unroll
        for (int ni = 0; ni < 8; ni++){
            int r0 = rowbase + mi * 16 + rlo;
            int c  = colbase + ni * 8 + cq;
            float2 v0 = make_float2(acc[mi][ni][0], acc[mi][ni][1]);
            float2 v1 = make_float2(acc[mi][ni][2], acc[mi][ni][3]);
            *reinterpret_cast<float2*>(&out[(size_t)r0 * D_OUTF + c])       = v0;
            *reinterpret_cast<float2*>(&out[(size_t)(r0 + 8) * D_OUTF + c]) = v1;
        }
    }
}

// ---------------- launch ----------------
extern "C" void kernel_launch(void* const* d_in, const int* in_sizes, int n_in,
                              void* d_out, int out_size){
    const float* x   = (const float*)d_in[0];   // [8192, 4096]
    const float* tkw = (const float*)d_in[1];   // [8192, 4]
    const float* W   = (const float*)d_in[2];   // [4096, 4096]
    const float* qa  = (const float*)d_in[3];   // [4, 8, 4096]
    const float* qb  = (const float*)d_in[4];   // [4, 4096, 8]
    const float* sf  = (const float*)d_in[5];   // [4, 4096]
    float* out = (float*)d_out;                 // [8192, 4096]

    fused_prep_kernel<<<LBLK + XBLK + WBLK + PBLK, 256>>>(x, W, qb, sf, qa);
    lora_fixup_kernel<<<N_TOK / 64, 256>>>(tkw);

    cudaFuncSetAttribute(gemm_hmma_kernel,
                         cudaFuncAttributeMaxDynamicSharedMemorySize, SMEM_TOTAL);
    gemm_hmma_kernel<<<M_TILES * N_TILES, 288, SMEM_TOTAL>>>(out);
}